// round 6
// baseline (speedup 1.0000x reference)
#include <cuda_runtime.h>
#include <cstdint>

#define NN      100000
#define NE      1600000
#define HID     256
#define KDIM    256
#define NSLOTS  800
#define SCAN_BLK 1024
#define NSCAN   ((NN + SCAN_BLK - 1) / SCAN_BLK)   // 98

// ---------------- scratch ----------------
__device__ __align__(128) float g_z  [(size_t)NN * HID];
__device__ __align__(128) float g_h  [(size_t)NN * HID];   // tf32-rounded tanh(agg1)
__device__ __align__(128) float g_ht [(size_t)NN * HID];   // tf32-rounded input h
__device__ __align__(128) float g_wt [2 * KDIM * HID];     // tf32-rounded W1, W2
__device__ __align__(128) float g_sums[NSLOTS * HID];
__device__ float g_cnt [NSLOTS];
__device__ int   g_deg [NN];
__device__ int   g_off [NN];
__device__ int   g_cursor[NN];
__device__ int   g_part[NSCAN];
__device__ int   g_csr [NE];

// ---------------- helpers ----------------
__device__ __forceinline__ void red_add_v4(float4* p, const float4 v) {
    asm volatile("red.global.add.v4.f32 [%0], {%1, %2, %3, %4};"
                 :: "l"(p), "f"(v.x), "f"(v.y), "f"(v.z), "f"(v.w)
                 : "memory");
}
__device__ __forceinline__ float4 tanh4(float4 v) {
    v.x = tanhf(v.x); v.y = tanhf(v.y); v.z = tanhf(v.z); v.w = tanhf(v.w);
    return v;
}
__device__ __forceinline__ uint32_t f2tf32(float f) {
    uint32_t r;
    asm("cvt.rna.tf32.f32 %0, %1;" : "=r"(r) : "f"(f));
    return r;
}
__device__ __forceinline__ float4 cvt4(float4 v) {
    v.x = __uint_as_float(f2tf32(v.x));
    v.y = __uint_as_float(f2tf32(v.y));
    v.z = __uint_as_float(f2tf32(v.z));
    v.w = __uint_as_float(f2tf32(v.w));
    return v;
}

// ---------------- zero / CSR build ----------------
__global__ void zero_misc_kernel() {
    int i = blockIdx.x * blockDim.x + threadIdx.x;
    if (i < NN)            g_deg[i]  = 0;
    if (i < NSLOTS * HID)  g_sums[i] = 0.f;
    if (i < NSLOTS)        g_cnt[i]  = 0.f;
}
__global__ void hist_kernel(const int* __restrict__ edst) {
    int e = blockIdx.x * blockDim.x + threadIdx.x;
    if (e < NE) atomicAdd(&g_deg[edst[e]], 1);
}
__global__ void scan1_kernel() {
    __shared__ int sh[256];
    int tid = threadIdx.x;
    int base = blockIdx.x * SCAN_BLK + tid * 4;
    int s = 0;
    if (base < NN) {
        int4 v = *reinterpret_cast<const int4*>(g_deg + base);
        s = v.x + v.y + v.z + v.w;
    }
    sh[tid] = s; __syncthreads();
    for (int o = 128; o > 0; o >>= 1) {
        if (tid < o) sh[tid] += sh[tid + o];
        __syncthreads();
    }
    if (tid == 0) g_part[blockIdx.x] = sh[0];
}
// warp-parallel exclusive scan of the 98 partials
__global__ void scan2_kernel() {
    int lane = threadIdx.x;                    // 32 threads
    int base = lane * 4;
    int v[4], tot = 0;
#pragma unroll
    for (int j = 0; j < 4; j++) {
        v[j] = (base + j < NSCAN) ? g_part[base + j] : 0;
        tot += v[j];
    }
    int inc = tot;
#pragma unroll
    for (int o = 1; o < 32; o <<= 1) {
        int n = __shfl_up_sync(0xFFFFFFFFu, inc, o);
        if (lane >= o) inc += n;
    }
    int run = inc - tot;                       // exclusive prefix
#pragma unroll
    for (int j = 0; j < 4; j++) {
        if (base + j < NSCAN) g_part[base + j] = run;
        run += v[j];
    }
}
__global__ void scan3_kernel() {
    __shared__ int sh[256];
    int tid = threadIdx.x;
    int base = blockIdx.x * SCAN_BLK + tid * 4;
    int4 v = make_int4(0, 0, 0, 0);
    if (base < NN) v = *reinterpret_cast<const int4*>(g_deg + base);
    int t = v.x + v.y + v.z + v.w;
    sh[tid] = t; __syncthreads();
    for (int o = 1; o < 256; o <<= 1) {
        int add = (tid >= o) ? sh[tid - o] : 0;
        __syncthreads();
        sh[tid] += add;
        __syncthreads();
    }
    int excl = sh[tid] - t + g_part[blockIdx.x];
    if (base < NN) {
        int4 o;
        o.x = excl; o.y = o.x + v.x; o.z = o.y + v.y; o.w = o.z + v.z;
        *reinterpret_cast<int4*>(g_off + base)    = o;
        *reinterpret_cast<int4*>(g_cursor + base) = o;
    }
}
__global__ void fill_csr_kernel(const int* __restrict__ esrc, const int* __restrict__ edst) {
    int e = blockIdx.x * blockDim.x + threadIdx.x;
    if (e >= NE) return;
    int d   = edst[e];
    int pos = atomicAdd(&g_cursor[d], 1);
    g_csr[pos] = esrc[e];
}

// ---------------- tf32 pre-conversion ----------------
__global__ void conv_h_kernel(const float* __restrict__ h) {
    size_t i = (size_t)blockIdx.x * 256 + threadIdx.x;     // 6,400,000 float4s
    reinterpret_cast<float4*>(g_ht)[i] = cvt4(reinterpret_cast<const float4*>(h)[i]);
}
__global__ void conv_w_kernel(const float* __restrict__ W1, const float* __restrict__ W2) {
    int i = blockIdx.x * 256 + threadIdx.x;                // 0..32767 float4s
    const float4* src = (i < 16384) ? reinterpret_cast<const float4*>(W1)
                                    : reinterpret_cast<const float4*>(W2) - 16384;
    reinterpret_cast<float4*>(g_wt)[i] = cvt4(src[i]);
}

// ---------------- tf32 mma.sync GEMM (cp.async 3-stage): g_z = A @ W + bias ----
#define BK      32
#define NCH     (KDIM / BK)            // 8
#define AS_STRIDE 36
#define BS_STRIDE 136
#define A_STG   (128 * AS_STRIDE)      // floats
#define B_STG   (BK * BS_STRIDE)
#define A_STG_B (A_STG * 4)            // 18432 B
#define B_STG_B (B_STG * 4)            // 17408 B
#define NSTAGE  3
#define GEMM_SMEM_BYTES (NSTAGE * (A_STG_B + B_STG_B))    // 107520

__device__ __forceinline__ void cp16(uint32_t dst, const void* src, int sz) {
    asm volatile("cp.async.cg.shared.global [%0], [%1], 16, %2;"
                 :: "r"(dst), "l"(src), "r"(sz));
}
__device__ __forceinline__ void cp_commit() {
    asm volatile("cp.async.commit_group;" ::: "memory");
}

__device__ __forceinline__ void mma_tf32(float* d, const uint32_t* a, const uint32_t* b) {
    asm volatile(
        "mma.sync.aligned.m16n8k8.row.col.f32.tf32.tf32.f32 "
        "{%0,%1,%2,%3}, {%4,%5,%6,%7}, {%8,%9}, {%0,%1,%2,%3};"
        : "+f"(d[0]), "+f"(d[1]), "+f"(d[2]), "+f"(d[3])
        : "r"(a[0]), "r"(a[1]), "r"(a[2]), "r"(a[3]), "r"(b[0]), "r"(b[1]));
}

__device__ __forceinline__ void gemm_fill_async(const float* __restrict__ A,
                                                const float* __restrict__ Wp,
                                                int m_base, int n_base, int M, int k0,
                                                uint32_t Au, uint32_t Bu, int tid) {
#pragma unroll
    for (int l = 0; l < 4; l++) {
        int idx = tid + l * 256;           // 0..1023
        int r   = idx >> 3;
        int c4  = (idx & 7) << 2;
        int gm  = m_base + r;
        int cg  = (gm < M) ? gm : 0;
        cp16(Au + (r * AS_STRIDE + c4) * 4,
             A + (size_t)cg * KDIM + k0 + c4, (gm < M) ? 16 : 0);
    }
#pragma unroll
    for (int l = 0; l < 4; l++) {
        int idx = tid + l * 256;           // 0..1023
        int k   = idx >> 5;
        int n4  = (idx & 31) << 2;
        cp16(Bu + (k * BS_STRIDE + n4) * 4,
             Wp + (size_t)(k0 + k) * HID + n_base + n4, 16);
    }
    cp_commit();
}

__global__ __launch_bounds__(256, 2)
void gemm_mma_kernel(const float* __restrict__ bias, int M, int a_sel, int w_sel) {
    extern __shared__ float smem[];
    const float* __restrict__ A  = a_sel ? g_h : g_ht;
    const float* __restrict__ Wp = g_wt + (size_t)w_sel * KDIM * HID;

    const int tid    = threadIdx.x;
    const int wid    = tid >> 5;
    const int lane   = tid & 31;
    const int warp_m = wid >> 2;
    const int warp_n = wid & 3;
    const int m_base = blockIdx.y * 128;
    const int n_base = blockIdx.x * 128;

    uint32_t smem_u = (uint32_t)__cvta_generic_to_shared(smem);
    const float* As[NSTAGE];
    const float* Bs[NSTAGE];
    uint32_t Au[NSTAGE], Bu[NSTAGE];
#pragma unroll
    for (int s = 0; s < NSTAGE; s++) {
        As[s] = smem + s * A_STG;
        Bs[s] = smem + NSTAGE * A_STG + s * B_STG;
        Au[s] = smem_u + s * A_STG_B;
        Bu[s] = smem_u + NSTAGE * A_STG_B + s * B_STG_B;
    }

    float acc[4][4][4];
#pragma unroll
    for (int i = 0; i < 4; i++)
#pragma unroll
        for (int j = 0; j < 4; j++)
#pragma unroll
            for (int f = 0; f < 4; f++) acc[i][j][f] = 0.f;

    gemm_fill_async(A, Wp, m_base, n_base, M, 0,      Au[0], Bu[0], tid);
    gemm_fill_async(A, Wp, m_base, n_base, M, BK,     Au[1], Bu[1], tid);

    const int g   = lane >> 2;
    const int cth = lane & 3;

    for (int c = 0; c < NCH; c++) {
        int s = c % NSTAGE;
        if (c == NCH - 1)
            asm volatile("cp.async.wait_group 0;" ::: "memory");
        else
            asm volatile("cp.async.wait_group 1;" ::: "memory");
        __syncthreads();

        if (c + 2 < NCH)
            gemm_fill_async(A, Wp, m_base, n_base, M, (c + 2) * BK,
                            Au[(c + 2) % NSTAGE], Bu[(c + 2) % NSTAGE], tid);

        const float* Ac = As[s];
        const float* Bc = Bs[s];
#pragma unroll
        for (int ks = 0; ks < 4; ks++) {
            uint32_t afr[4][4], bfr[4][2];
#pragma unroll
            for (int mt = 0; mt < 4; mt++) {
                const float* p = Ac + (warp_m * 64 + mt * 16 + g) * AS_STRIDE + ks * 8 + cth;
                afr[mt][0] = __float_as_uint(p[0]);
                afr[mt][1] = __float_as_uint(p[8 * AS_STRIDE]);
                afr[mt][2] = __float_as_uint(p[4]);
                afr[mt][3] = __float_as_uint(p[8 * AS_STRIDE + 4]);
            }
#pragma unroll
            for (int nt = 0; nt < 4; nt++) {
                const float* p = Bc + (ks * 8 + cth) * BS_STRIDE + warp_n * 32 + nt * 8 + g;
                bfr[nt][0] = __float_as_uint(p[0]);
                bfr[nt][1] = __float_as_uint(p[4 * BS_STRIDE]);
            }
#pragma unroll
            for (int mt = 0; mt < 4; mt++)
#pragma unroll
                for (int nt = 0; nt < 4; nt++)
                    mma_tf32(acc[mt][nt], afr[mt], bfr[nt]);
        }
    }

#pragma unroll
    for (int mt = 0; mt < 4; mt++) {
        int r0 = m_base + warp_m * 64 + mt * 16 + g;
        int r1 = r0 + 8;
#pragma unroll
        for (int nt = 0; nt < 4; nt++) {
            int col = n_base + warp_n * 32 + nt * 8 + cth * 2;
            float b0 = __ldg(bias + col);
            float b1 = __ldg(bias + col + 1);
            if (r0 < M) {
                float2 o = make_float2(acc[mt][nt][0] + b0, acc[mt][nt][1] + b1);
                *reinterpret_cast<float2*>(g_z + (size_t)r0 * HID + col) = o;
            }
            if (r1 < M) {
                float2 o = make_float2(acc[mt][nt][2] + b0, acc[mt][nt][3] + b1);
                *reinterpret_cast<float2*>(g_z + (size_t)r1 * HID + col) = o;
            }
        }
    }
}

// ---------------- gather-aggregate (CSR), warp per dst node ----------------
__device__ __forceinline__ void gather_node(int node, int lane, float4& a0, float4& a1) {
    int start = g_off[node];
    int d     = g_deg[node];
    const float4* Z = reinterpret_cast<const float4*>(g_z);
    a0 = make_float4(0.f, 0.f, 0.f, 0.f);
    a1 = make_float4(0.f, 0.f, 0.f, 0.f);
    int i = 0;
    for (; i + 2 <= d; i += 2) {
        int s0 = __ldg(&g_csr[start + i]);
        int s1 = __ldg(&g_csr[start + i + 1]);
        float4 v00 = __ldg(Z + (size_t)s0 * 64 + lane);
        float4 v01 = __ldg(Z + (size_t)s0 * 64 + lane + 32);
        float4 v10 = __ldg(Z + (size_t)s1 * 64 + lane);
        float4 v11 = __ldg(Z + (size_t)s1 * 64 + lane + 32);
        a0.x += v00.x; a0.y += v00.y; a0.z += v00.z; a0.w += v00.w;
        a1.x += v01.x; a1.y += v01.y; a1.z += v01.z; a1.w += v01.w;
        a0.x += v10.x; a0.y += v10.y; a0.z += v10.z; a0.w += v10.w;
        a1.x += v11.x; a1.y += v11.y; a1.z += v11.z; a1.w += v11.w;
    }
    if (i < d) {
        int s0 = __ldg(&g_csr[start + i]);
        float4 v00 = __ldg(Z + (size_t)s0 * 64 + lane);
        float4 v01 = __ldg(Z + (size_t)s0 * 64 + lane + 32);
        a0.x += v00.x; a0.y += v00.y; a0.z += v00.z; a0.w += v00.w;
        a1.x += v01.x; a1.y += v01.y; a1.z += v01.z; a1.w += v01.w;
    }
}

__global__ void agg1_kernel() {
    int node = (blockIdx.x * blockDim.x + threadIdx.x) >> 5;
    int lane = threadIdx.x & 31;
    if (node >= NN) return;
    float4 a0, a1;
    gather_node(node, lane, a0, a1);
    float4* H = reinterpret_cast<float4*>(g_h) + (size_t)node * 64;
    __stcs(H + lane,      cvt4(tanh4(a0)));   // tf32-rounded for GEMM2 cp.async path
    __stcs(H + lane + 32, cvt4(tanh4(a1)));
}

__global__ void agg2_pool_kernel(const int* __restrict__ seg) {
    int node = (blockIdx.x * blockDim.x + threadIdx.x) >> 5;
    int lane = threadIdx.x & 31;
    if (node >= NN) return;
    float4 a0, a1;
    gather_node(node, lane, a0, a1);
    int s = __ldg(seg + node);
    float4* dp = reinterpret_cast<float4*>(g_sums) + (size_t)s * 64;
    red_add_v4(dp + lane,      tanh4(a0));
    red_add_v4(dp + lane + 32, tanh4(a1));
    if (lane == 0) atomicAdd(&g_cnt[s], 1.0f);
}

__global__ void finalize_kernel(float* __restrict__ out) {
    int i = blockIdx.x * blockDim.x + threadIdx.x;
    if (i < NSLOTS * HID) {
        float c = g_cnt[i >> 8];
        out[i] = g_sums[i] / fmaxf(c, 1.0f);
    }
}

// ---------------- launch ----------------
extern "C" void kernel_launch(void* const* d_in, const int* in_sizes, int n_in,
                              void* d_out, int out_size) {
    const float* h    = (const float*)d_in[0];
    const float* W1   = (const float*)d_in[1];
    const float* b1   = (const float*)d_in[2];
    const float* W2   = (const float*)d_in[3];
    const float* b2   = (const float*)d_in[4];
    const int*   esrc = (const int*)d_in[5];
    const int*   edst = (const int*)d_in[6];
    const int*   seg  = (const int*)d_in[7];
    float*       out  = (float*)d_out;

    const int M = in_sizes[0] / HID;   // 100000

    static cudaStream_t s2 = nullptr;
    static cudaEvent_t  evA = nullptr, evB = nullptr;
    static int inited = 0;
    if (!inited) {
        cudaStreamCreateWithFlags(&s2, cudaStreamNonBlocking);
        cudaEventCreateWithFlags(&evA, cudaEventDisableTiming);
        cudaEventCreateWithFlags(&evB, cudaEventDisableTiming);
        cudaFuncSetAttribute(gemm_mma_kernel,
                             cudaFuncAttributeMaxDynamicSharedMemorySize,
                             GEMM_SMEM_BYTES);
        inited = 1;
    }

    dim3 gemm_grid(HID / 128, (M + 127) / 128);        // (2, 782)
    int  agg_blocks  = (M * 32 + 255) / 256;
    int  edge_blocks = (NE + 255) / 256;

    // ---- fork: CSR build on side stream ----
    cudaEventRecord(evA, 0);
    cudaStreamWaitEvent(s2, evA, 0);
    zero_misc_kernel<<<(NSLOTS * HID + 255) / 256, 256, 0, s2>>>();
    hist_kernel<<<edge_blocks, 256, 0, s2>>>(edst);
    scan1_kernel<<<NSCAN, 256, 0, s2>>>();
    scan2_kernel<<<1, 32, 0, s2>>>();
    scan3_kernel<<<NSCAN, 256, 0, s2>>>();
    fill_csr_kernel<<<edge_blocks, 256, 0, s2>>>(esrc, edst);
    cudaEventRecord(evB, s2);

    // ---- main stream: convert + GEMM1 (independent of CSR) ----
    conv_h_kernel<<<(NN * HID / 4) / 256, 256>>>(h);
    conv_w_kernel<<<128, 256>>>(W1, W2);
    gemm_mma_kernel<<<gemm_grid, 256, GEMM_SMEM_BYTES>>>(b1, M, 0, 0);

    // ---- join: CSR needed from here on ----
    cudaStreamWaitEvent(0, evB, 0);
    agg1_kernel<<<agg_blocks, 256>>>();

    gemm_mma_kernel<<<gemm_grid, 256, GEMM_SMEM_BYTES>>>(b2, M, 1, 1);
    agg2_pool_kernel<<<agg_blocks, 256>>>(seg);

    finalize_kernel<<<(NSLOTS * HID + 255) / 256, 256>>>(out);
}

// round 7
// speedup vs baseline: 1.1079x; 1.1079x over previous
#include <cuda_runtime.h>
#include <cstdint>

#define NN      100000
#define NE      1600000
#define HID     256
#define KDIM    256
#define NSLOTS  800
#define SCAN_BLK 1024
#define NSCAN   ((NN + SCAN_BLK - 1) / SCAN_BLK)   // 98

// ---------------- scratch ----------------
__device__ __align__(128) float g_z  [(size_t)NN * HID];
__device__ __align__(128) float g_h  [(size_t)NN * HID];
__device__ __align__(128) float g_sums[NSLOTS * HID];
__device__ float g_cnt [NSLOTS];
__device__ int   g_deg [NN];
__device__ int   g_off [NN];
__device__ int   g_cursor[NN];
__device__ int   g_part[NSCAN];
__device__ int   g_csr [NE];

// ---------------- helpers ----------------
__device__ __forceinline__ void red_add_v4(float4* p, const float4 v) {
    asm volatile("red.global.add.v4.f32 [%0], {%1, %2, %3, %4};"
                 :: "l"(p), "f"(v.x), "f"(v.y), "f"(v.z), "f"(v.w)
                 : "memory");
}
__device__ __forceinline__ float4 tanh4(float4 v) {
    v.x = tanhf(v.x); v.y = tanhf(v.y); v.z = tanhf(v.z); v.w = tanhf(v.w);
    return v;
}
__device__ __forceinline__ uint32_t f2tf32(float f) {
    uint32_t r;
    asm("cvt.rna.tf32.f32 %0, %1;" : "=r"(r) : "f"(f));
    return r;
}
__device__ __forceinline__ void acc4(float4& a, const float4 v) {
    a.x += v.x; a.y += v.y; a.z += v.z; a.w += v.w;
}

// ---------------- zero / CSR build ----------------
__global__ void zero_misc_kernel() {
    int i = blockIdx.x * blockDim.x + threadIdx.x;
    if (i < NN)            g_deg[i]  = 0;
    if (i < NSLOTS * HID)  g_sums[i] = 0.f;
    if (i < NSLOTS)        g_cnt[i]  = 0.f;
}
__global__ void hist_kernel(const int* __restrict__ edst) {
    int e = blockIdx.x * blockDim.x + threadIdx.x;
    if (e < NE) atomicAdd(&g_deg[edst[e]], 1);
}
__global__ void scan1_kernel() {
    __shared__ int sh[256];
    int tid = threadIdx.x;
    int base = blockIdx.x * SCAN_BLK + tid * 4;
    int s = 0;
    if (base < NN) {
        int4 v = *reinterpret_cast<const int4*>(g_deg + base);
        s = v.x + v.y + v.z + v.w;
    }
    sh[tid] = s; __syncthreads();
    for (int o = 128; o > 0; o >>= 1) {
        if (tid < o) sh[tid] += sh[tid + o];
        __syncthreads();
    }
    if (tid == 0) g_part[blockIdx.x] = sh[0];
}
__global__ void scan2_kernel() {
    int lane = threadIdx.x;                    // 32 threads
    int base = lane * 4;
    int v[4], tot = 0;
#pragma unroll
    for (int j = 0; j < 4; j++) {
        v[j] = (base + j < NSCAN) ? g_part[base + j] : 0;
        tot += v[j];
    }
    int inc = tot;
#pragma unroll
    for (int o = 1; o < 32; o <<= 1) {
        int n = __shfl_up_sync(0xFFFFFFFFu, inc, o);
        if (lane >= o) inc += n;
    }
    int run = inc - tot;
#pragma unroll
    for (int j = 0; j < 4; j++) {
        if (base + j < NSCAN) g_part[base + j] = run;
        run += v[j];
    }
}
__global__ void scan3_kernel() {
    __shared__ int sh[256];
    int tid = threadIdx.x;
    int base = blockIdx.x * SCAN_BLK + tid * 4;
    int4 v = make_int4(0, 0, 0, 0);
    if (base < NN) v = *reinterpret_cast<const int4*>(g_deg + base);
    int t = v.x + v.y + v.z + v.w;
    sh[tid] = t; __syncthreads();
    for (int o = 1; o < 256; o <<= 1) {
        int add = (tid >= o) ? sh[tid - o] : 0;
        __syncthreads();
        sh[tid] += add;
        __syncthreads();
    }
    int excl = sh[tid] - t + g_part[blockIdx.x];
    if (base < NN) {
        int4 o;
        o.x = excl; o.y = o.x + v.x; o.z = o.y + v.y; o.w = o.z + v.z;
        *reinterpret_cast<int4*>(g_off + base)    = o;
        *reinterpret_cast<int4*>(g_cursor + base) = o;
    }
}
__global__ void fill_csr_kernel(const int* __restrict__ esrc, const int* __restrict__ edst) {
    int e = blockIdx.x * blockDim.x + threadIdx.x;
    if (e >= NE) return;
    int d   = edst[e];
    int pos = atomicAdd(&g_cursor[d], 1);
    g_csr[pos] = esrc[e];
}

// ---------------- tf32 mma.sync GEMM (R5 cvt-fill, 2-stage): g_z = A @ W + b --
#define BK      32
#define NCH     (KDIM / BK)            // 8
#define AS_STRIDE 36
#define BS_STRIDE 136
#define A_STG   (128 * AS_STRIDE)
#define B_STG   (BK * BS_STRIDE)
#define GEMM_SMEM_BYTES ((2 * A_STG + 2 * B_STG) * 4)   // 71680

__device__ __forceinline__ void mma_tf32(float* d, const uint32_t* a, const uint32_t* b) {
    asm volatile(
        "mma.sync.aligned.m16n8k8.row.col.f32.tf32.tf32.f32 "
        "{%0,%1,%2,%3}, {%4,%5,%6,%7}, {%8,%9}, {%0,%1,%2,%3};"
        : "+f"(d[0]), "+f"(d[1]), "+f"(d[2]), "+f"(d[3])
        : "r"(a[0]), "r"(a[1]), "r"(a[2]), "r"(a[3]), "r"(b[0]), "r"(b[1]));
}

__device__ __forceinline__ void gemm_fill(const float* __restrict__ A,
                                          const float* __restrict__ W,
                                          int m_base, int n_base, int M, int k0,
                                          float* Af, float* Bf, int tid) {
#pragma unroll
    for (int l = 0; l < 4; l++) {
        int idx = tid + l * 256;
        int r   = idx >> 3;
        int c4  = (idx & 7) << 2;
        int gm  = m_base + r;
        float4 v = make_float4(0.f, 0.f, 0.f, 0.f);
        if (gm < M)
            v = *reinterpret_cast<const float4*>(A + (size_t)gm * KDIM + k0 + c4);
        uint4 t;
        t.x = f2tf32(v.x); t.y = f2tf32(v.y); t.z = f2tf32(v.z); t.w = f2tf32(v.w);
        *reinterpret_cast<uint4*>(Af + r * AS_STRIDE + c4) = t;
    }
#pragma unroll
    for (int l = 0; l < 4; l++) {
        int idx = tid + l * 256;
        int k   = idx >> 5;
        int n4  = (idx & 31) << 2;
        float4 v = *reinterpret_cast<const float4*>(
            W + (size_t)(k0 + k) * HID + n_base + n4);
        uint4 t;
        t.x = f2tf32(v.x); t.y = f2tf32(v.y); t.z = f2tf32(v.z); t.w = f2tf32(v.w);
        *reinterpret_cast<uint4*>(Bf + k * BS_STRIDE + n4) = t;
    }
}

__global__ __launch_bounds__(256, 2)
void gemm_mma_kernel(const float* __restrict__ A_in, const float* __restrict__ W,
                     const float* __restrict__ bias, int M, int useGH) {
    extern __shared__ float smem[];
    const float* __restrict__ A = useGH ? g_h : A_in;

    const int tid    = threadIdx.x;
    const int wid    = tid >> 5;
    const int lane   = tid & 31;
    const int warp_m = wid >> 2;
    const int warp_n = wid & 3;
    const int m_base = blockIdx.y * 128;
    const int n_base = blockIdx.x * 128;

    float* Asm[2] = { smem,             smem + A_STG };
    float* Bsm[2] = { smem + 2 * A_STG, smem + 2 * A_STG + B_STG };

    float acc[4][4][4];
#pragma unroll
    for (int i = 0; i < 4; i++)
#pragma unroll
        for (int j = 0; j < 4; j++)
#pragma unroll
            for (int f = 0; f < 4; f++) acc[i][j][f] = 0.f;

    gemm_fill(A, W, m_base, n_base, M, 0, Asm[0], Bsm[0], tid);
    __syncthreads();

    const int g   = lane >> 2;
    const int cth = lane & 3;

    for (int c = 0; c < NCH; c++) {
        int cur = c & 1;
        const float* As = Asm[cur];
        const float* Bs = Bsm[cur];

        if (c + 1 < NCH)
            gemm_fill(A, W, m_base, n_base, M, (c + 1) * BK,
                      Asm[1 - cur], Bsm[1 - cur], tid);

#pragma unroll
        for (int ks = 0; ks < 4; ks++) {
            uint32_t afr[4][4], bfr[4][2];
#pragma unroll
            for (int mt = 0; mt < 4; mt++) {
                const float* p = As + (warp_m * 64 + mt * 16 + g) * AS_STRIDE + ks * 8 + cth;
                afr[mt][0] = __float_as_uint(p[0]);
                afr[mt][1] = __float_as_uint(p[8 * AS_STRIDE]);
                afr[mt][2] = __float_as_uint(p[4]);
                afr[mt][3] = __float_as_uint(p[8 * AS_STRIDE + 4]);
            }
#pragma unroll
            for (int nt = 0; nt < 4; nt++) {
                const float* p = Bs + (ks * 8 + cth) * BS_STRIDE + warp_n * 32 + nt * 8 + g;
                bfr[nt][0] = __float_as_uint(p[0]);
                bfr[nt][1] = __float_as_uint(p[4 * BS_STRIDE]);
            }
#pragma unroll
            for (int mt = 0; mt < 4; mt++)
#pragma unroll
                for (int nt = 0; nt < 4; nt++)
                    mma_tf32(acc[mt][nt], afr[mt], bfr[nt]);
        }
        __syncthreads();
    }

#pragma unroll
    for (int mt = 0; mt < 4; mt++) {
        int r0 = m_base + warp_m * 64 + mt * 16 + g;
        int r1 = r0 + 8;
#pragma unroll
        for (int nt = 0; nt < 4; nt++) {
            int col = n_base + warp_n * 32 + nt * 8 + cth * 2;
            float b0 = __ldg(bias + col);
            float b1 = __ldg(bias + col + 1);
            if (r0 < M) {
                float2 o = make_float2(acc[mt][nt][0] + b0, acc[mt][nt][1] + b1);
                *reinterpret_cast<float2*>(g_z + (size_t)r0 * HID + col) = o;
            }
            if (r1 < M) {
                float2 o = make_float2(acc[mt][nt][2] + b0, acc[mt][nt][3] + b1);
                *reinterpret_cast<float2*>(g_z + (size_t)r1 * HID + col) = o;
            }
        }
    }
}

// ---------------- column-blocked gather-aggregate (CSR), warp/node/half ------
// Each pass touches only a 51MB slice of g_z -> L2-resident reads.
__device__ __forceinline__ float4 gather_half(int node, int lane4) {
    int start = g_off[node];
    int d     = g_deg[node];
    const float4* Z = reinterpret_cast<const float4*>(g_z);
    float4 a = make_float4(0.f, 0.f, 0.f, 0.f);
    int i = 0;
    for (; i + 4 <= d; i += 4) {
        int s0 = __ldg(&g_csr[start + i]);
        int s1 = __ldg(&g_csr[start + i + 1]);
        int s2 = __ldg(&g_csr[start + i + 2]);
        int s3 = __ldg(&g_csr[start + i + 3]);
        float4 v0 = __ldg(Z + (size_t)s0 * 64 + lane4);
        float4 v1 = __ldg(Z + (size_t)s1 * 64 + lane4);
        float4 v2 = __ldg(Z + (size_t)s2 * 64 + lane4);
        float4 v3 = __ldg(Z + (size_t)s3 * 64 + lane4);
        acc4(a, v0); acc4(a, v1); acc4(a, v2); acc4(a, v3);
    }
    for (; i < d; i++) {
        int s0 = __ldg(&g_csr[start + i]);
        acc4(a, __ldg(Z + (size_t)s0 * 64 + lane4));
    }
    return a;
}

__global__ void agg1_half_kernel(int half) {
    int node = (blockIdx.x * blockDim.x + threadIdx.x) >> 5;
    int lane = threadIdx.x & 31;
    if (node >= NN) return;
    int lane4 = half * 32 + lane;
    float4 a = gather_half(node, lane4);
    float4* H = reinterpret_cast<float4*>(g_h) + (size_t)node * 64;
    __stcs(H + lane4, tanh4(a));
}

__global__ void agg2_pool_half_kernel(const int* __restrict__ seg, int half) {
    int node = (blockIdx.x * blockDim.x + threadIdx.x) >> 5;
    int lane = threadIdx.x & 31;
    if (node >= NN) return;
    int lane4 = half * 32 + lane;
    float4 a = gather_half(node, lane4);
    int s = __ldg(seg + node);
    float4* dp = reinterpret_cast<float4*>(g_sums) + (size_t)s * 64;
    red_add_v4(dp + lane4, tanh4(a));
    if (half == 0 && lane == 0) atomicAdd(&g_cnt[s], 1.0f);
}

__global__ void finalize_kernel(float* __restrict__ out) {
    int i = blockIdx.x * blockDim.x + threadIdx.x;
    if (i < NSLOTS * HID) {
        float c = g_cnt[i >> 8];
        out[i] = g_sums[i] / fmaxf(c, 1.0f);
    }
}

// ---------------- launch ----------------
extern "C" void kernel_launch(void* const* d_in, const int* in_sizes, int n_in,
                              void* d_out, int out_size) {
    const float* h    = (const float*)d_in[0];
    const float* W1   = (const float*)d_in[1];
    const float* b1   = (const float*)d_in[2];
    const float* W2   = (const float*)d_in[3];
    const float* b2   = (const float*)d_in[4];
    const int*   esrc = (const int*)d_in[5];
    const int*   edst = (const int*)d_in[6];
    const int*   seg  = (const int*)d_in[7];
    float*       out  = (float*)d_out;

    const int M = in_sizes[0] / HID;   // 100000

    static cudaStream_t s2 = nullptr;
    static cudaEvent_t  evA = nullptr, evB = nullptr;
    static int inited = 0;
    if (!inited) {
        cudaStreamCreateWithFlags(&s2, cudaStreamNonBlocking);
        cudaEventCreateWithFlags(&evA, cudaEventDisableTiming);
        cudaEventCreateWithFlags(&evB, cudaEventDisableTiming);
        cudaFuncSetAttribute(gemm_mma_kernel,
                             cudaFuncAttributeMaxDynamicSharedMemorySize,
                             GEMM_SMEM_BYTES);
        inited = 1;
    }

    dim3 gemm_grid(HID / 128, (M + 127) / 128);        // (2, 782)
    int  agg_blocks  = (M * 32 + 255) / 256;
    int  edge_blocks = (NE + 255) / 256;

    // ---- fork: CSR build on side stream ----
    cudaEventRecord(evA, 0);
    cudaStreamWaitEvent(s2, evA, 0);
    zero_misc_kernel<<<(NSLOTS * HID + 255) / 256, 256, 0, s2>>>();
    hist_kernel<<<edge_blocks, 256, 0, s2>>>(edst);
    scan1_kernel<<<NSCAN, 256, 0, s2>>>();
    scan2_kernel<<<1, 32, 0, s2>>>();
    scan3_kernel<<<NSCAN, 256, 0, s2>>>();
    fill_csr_kernel<<<edge_blocks, 256, 0, s2>>>(esrc, edst);
    cudaEventRecord(evB, s2);

    // ---- main stream: GEMM1 (independent of CSR) ----
    gemm_mma_kernel<<<gemm_grid, 256, GEMM_SMEM_BYTES>>>(h, W1, b1, M, 0);

    // ---- join: CSR needed from here on ----
    cudaStreamWaitEvent(0, evB, 0);
    agg1_half_kernel<<<agg_blocks, 256>>>(0);
    agg1_half_kernel<<<agg_blocks, 256>>>(1);

    gemm_mma_kernel<<<gemm_grid, 256, GEMM_SMEM_BYTES>>>(h, W2, b2, M, 1);
    agg2_pool_half_kernel<<<agg_blocks, 256>>>(seg, 0);
    agg2_pool_half_kernel<<<agg_blocks, 256>>>(seg, 1);

    finalize_kernel<<<(NSLOTS * HID + 255) / 256, 256>>>(out);
}

// round 9
// speedup vs baseline: 1.1225x; 1.0132x over previous
#include <cuda_runtime.h>
#include <cuda_fp16.h>
#include <cstdint>

#define NN      100000
#define NE      1600000
#define HID     256
#define KDIM    256
#define NSLOTS  800
#define SCAN_BLK 1024
#define NSCAN   ((NN + SCAN_BLK - 1) / SCAN_BLK)   // 98

// ---------------- scratch ----------------
__device__ __align__(128) __half g_z16[(size_t)NN * HID];   // GEMM out (fp16)
__device__ __align__(128) __half g_h16[(size_t)NN * HID];   // tanh(agg1) (fp16)
__device__ __align__(128) float  g_sums[NSLOTS * HID];
__device__ float g_cnt [NSLOTS];
__device__ int   g_deg [NN];
__device__ int   g_off [NN];
__device__ int   g_cursor[NN];
__device__ int   g_part[NSCAN];
__device__ int   g_csr [NE];

// ---------------- helpers ----------------
__device__ __forceinline__ void red_add_v4(float4* p, const float4 v) {
    asm volatile("red.global.add.v4.f32 [%0], {%1, %2, %3, %4};"
                 :: "l"(p), "f"(v.x), "f"(v.y), "f"(v.z), "f"(v.w)
                 : "memory");
}
__device__ __forceinline__ uint32_t f2tf32(float f) {
    uint32_t r;
    asm("cvt.rna.tf32.f32 %0, %1;" : "=r"(r) : "f"(f));
    return r;
}

// ---------------- zero / CSR build ----------------
__global__ void zero_misc_kernel() {
    int i = blockIdx.x * blockDim.x + threadIdx.x;
    if (i < NN)            g_deg[i]  = 0;
    if (i < NSLOTS * HID)  g_sums[i] = 0.f;
    if (i < NSLOTS)        g_cnt[i]  = 0.f;
}
__global__ void hist_kernel(const int* __restrict__ edst) {
    int e = blockIdx.x * blockDim.x + threadIdx.x;
    if (e < NE) atomicAdd(&g_deg[edst[e]], 1);
}
__global__ void scan1_kernel() {
    __shared__ int sh[256];
    int tid = threadIdx.x;
    int base = blockIdx.x * SCAN_BLK + tid * 4;
    int s = 0;
    if (base < NN) {
        int4 v = *reinterpret_cast<const int4*>(g_deg + base);
        s = v.x + v.y + v.z + v.w;
    }
    sh[tid] = s; __syncthreads();
    for (int o = 128; o > 0; o >>= 1) {
        if (tid < o) sh[tid] += sh[tid + o];
        __syncthreads();
    }
    if (tid == 0) g_part[blockIdx.x] = sh[0];
}
__global__ void scan2_kernel() {
    int lane = threadIdx.x;
    int base = lane * 4;
    int v[4], tot = 0;
#pragma unroll
    for (int j = 0; j < 4; j++) {
        v[j] = (base + j < NSCAN) ? g_part[base + j] : 0;
        tot += v[j];
    }
    int inc = tot;
#pragma unroll
    for (int o = 1; o < 32; o <<= 1) {
        int n = __shfl_up_sync(0xFFFFFFFFu, inc, o);
        if (lane >= o) inc += n;
    }
    int run = inc - tot;
#pragma unroll
    for (int j = 0; j < 4; j++) {
        if (base + j < NSCAN) g_part[base + j] = run;
        run += v[j];
    }
}
__global__ void scan3_kernel() {
    __shared__ int sh[256];
    int tid = threadIdx.x;
    int base = blockIdx.x * SCAN_BLK + tid * 4;
    int4 v = make_int4(0, 0, 0, 0);
    if (base < NN) v = *reinterpret_cast<const int4*>(g_deg + base);
    int t = v.x + v.y + v.z + v.w;
    sh[tid] = t; __syncthreads();
    for (int o = 1; o < 256; o <<= 1) {
        int add = (tid >= o) ? sh[tid - o] : 0;
        __syncthreads();
        sh[tid] += add;
        __syncthreads();
    }
    int excl = sh[tid] - t + g_part[blockIdx.x];
    if (base < NN) {
        int4 o;
        o.x = excl; o.y = o.x + v.x; o.z = o.y + v.y; o.w = o.z + v.z;
        *reinterpret_cast<int4*>(g_off + base)    = o;
        *reinterpret_cast<int4*>(g_cursor + base) = o;
    }
}
__global__ void fill_csr_kernel(const int* __restrict__ esrc, const int* __restrict__ edst) {
    int e = blockIdx.x * blockDim.x + threadIdx.x;
    if (e >= NE) return;
    int d   = edst[e];
    int pos = atomicAdd(&g_cursor[d], 1);
    g_csr[pos] = esrc[e];
}

// ---------------- tf32 mma.sync GEMM: g_z16 = fp16(A @ W + bias) ----------------
#define BK      32
#define NCH     (KDIM / BK)
#define AS_STRIDE 36
#define BS_STRIDE 136
#define A_STG   (128 * AS_STRIDE)
#define B_STG   (BK * BS_STRIDE)
#define GEMM_SMEM_BYTES ((2 * A_STG + 2 * B_STG) * 4)   // 71680

__device__ __forceinline__ void mma_tf32(float* d, const uint32_t* a, const uint32_t* b) {
    asm volatile(
        "mma.sync.aligned.m16n8k8.row.col.f32.tf32.tf32.f32 "
        "{%0,%1,%2,%3}, {%4,%5,%6,%7}, {%8,%9}, {%0,%1,%2,%3};"
        : "+f"(d[0]), "+f"(d[1]), "+f"(d[2]), "+f"(d[3])
        : "r"(a[0]), "r"(a[1]), "r"(a[2]), "r"(a[3]), "r"(b[0]), "r"(b[1]));
}

// A source: fp32 (layer 1, external h) or fp16 (layer 2, g_h16)
__device__ __forceinline__ void gemm_fill(const float* __restrict__ A32, int useGH,
                                          const float* __restrict__ W,
                                          int m_base, int n_base, int M, int k0,
                                          float* Af, float* Bf, int tid) {
#pragma unroll
    for (int l = 0; l < 4; l++) {
        int idx = tid + l * 256;
        int r   = idx >> 3;
        int c4  = (idx & 7) << 2;
        int gm  = m_base + r;
        float4 v = make_float4(0.f, 0.f, 0.f, 0.f);
        if (gm < M) {
            if (useGH) {
                uint2 raw = __ldg(reinterpret_cast<const uint2*>(
                    g_h16 + (size_t)gm * KDIM + k0 + c4));
                __half2 h0 = *reinterpret_cast<__half2*>(&raw.x);
                __half2 h1 = *reinterpret_cast<__half2*>(&raw.y);
                float2 f0 = __half22float2(h0);
                float2 f1 = __half22float2(h1);
                v = make_float4(f0.x, f0.y, f1.x, f1.y);
            } else {
                v = *reinterpret_cast<const float4*>(A32 + (size_t)gm * KDIM + k0 + c4);
            }
        }
        uint4 t;
        t.x = f2tf32(v.x); t.y = f2tf32(v.y); t.z = f2tf32(v.z); t.w = f2tf32(v.w);
        *reinterpret_cast<uint4*>(Af + r * AS_STRIDE + c4) = t;
    }
#pragma unroll
    for (int l = 0; l < 4; l++) {
        int idx = tid + l * 256;
        int k   = idx >> 5;
        int n4  = (idx & 31) << 2;
        float4 v = *reinterpret_cast<const float4*>(
            W + (size_t)(k0 + k) * HID + n_base + n4);
        uint4 t;
        t.x = f2tf32(v.x); t.y = f2tf32(v.y); t.z = f2tf32(v.z); t.w = f2tf32(v.w);
        *reinterpret_cast<uint4*>(Bf + k * BS_STRIDE + n4) = t;
    }
}

__global__ __launch_bounds__(256, 2)
void gemm_mma_kernel(const float* __restrict__ A_in, const float* __restrict__ W,
                     const float* __restrict__ bias, int M, int useGH) {
    extern __shared__ float smem[];

    const int tid    = threadIdx.x;
    const int wid    = tid >> 5;
    const int lane   = tid & 31;
    const int warp_m = wid >> 2;
    const int warp_n = wid & 3;
    const int m_base = blockIdx.y * 128;
    const int n_base = blockIdx.x * 128;

    float* Asm[2] = { smem,             smem + A_STG };
    float* Bsm[2] = { smem + 2 * A_STG, smem + 2 * A_STG + B_STG };

    float acc[4][4][4];
#pragma unroll
    for (int i = 0; i < 4; i++)
#pragma unroll
        for (int j = 0; j < 4; j++)
#pragma unroll
            for (int f = 0; f < 4; f++) acc[i][j][f] = 0.f;

    gemm_fill(A_in, useGH, W, m_base, n_base, M, 0, Asm[0], Bsm[0], tid);
    __syncthreads();

    const int g   = lane >> 2;
    const int cth = lane & 3;

    for (int c = 0; c < NCH; c++) {
        int cur = c & 1;
        const float* As = Asm[cur];
        const float* Bs = Bsm[cur];

        if (c + 1 < NCH)
            gemm_fill(A_in, useGH, W, m_base, n_base, M, (c + 1) * BK,
                      Asm[1 - cur], Bsm[1 - cur], tid);

#pragma unroll
        for (int ks = 0; ks < 4; ks++) {
            uint32_t afr[4][4], bfr[4][2];
#pragma unroll
            for (int mt = 0; mt < 4; mt++) {
                const float* p = As + (warp_m * 64 + mt * 16 + g) * AS_STRIDE + ks * 8 + cth;
                afr[mt][0] = __float_as_uint(p[0]);
                afr[mt][1] = __float_as_uint(p[8 * AS_STRIDE]);
                afr[mt][2] = __float_as_uint(p[4]);
                afr[mt][3] = __float_as_uint(p[8 * AS_STRIDE + 4]);
            }
#pragma unroll
            for (int nt = 0; nt < 4; nt++) {
                const float* p = Bs + (ks * 8 + cth) * BS_STRIDE + warp_n * 32 + nt * 8 + g;
                bfr[nt][0] = __float_as_uint(p[0]);
                bfr[nt][1] = __float_as_uint(p[4 * BS_STRIDE]);
            }
#pragma unroll
            for (int mt = 0; mt < 4; mt++)
#pragma unroll
                for (int nt = 0; nt < 4; nt++)
                    mma_tf32(acc[mt][nt], afr[mt], bfr[nt]);
        }
        __syncthreads();
    }

    // epilogue: round to fp16, store half2 (4B) per fragment pair
#pragma unroll
    for (int mt = 0; mt < 4; mt++) {
        int r0 = m_base + warp_m * 64 + mt * 16 + g;
        int r1 = r0 + 8;
#pragma unroll
        for (int nt = 0; nt < 4; nt++) {
            int col = n_base + warp_n * 32 + nt * 8 + cth * 2;
            float b0 = __ldg(bias + col);
            float b1 = __ldg(bias + col + 1);
            if (r0 < M) {
                __half2 o = __floats2half2_rn(acc[mt][nt][0] + b0, acc[mt][nt][1] + b1);
                *reinterpret_cast<__half2*>(g_z16 + (size_t)r0 * HID + col) = o;
            }
            if (r1 < M) {
                __half2 o = __floats2half2_rn(acc[mt][nt][2] + b0, acc[mt][nt][3] + b1);
                *reinterpret_cast<__half2*>(g_z16 + (size_t)r1 * HID + col) = o;
            }
        }
    }
}

// ---------------- fp16 gather-aggregate (CSR), warp per node, full row -------
// Each lane handles 8 channels (16B of fp16 per src row). z16 table = 51MB,
// fully L2-resident -> reads at L2 bandwidth.
__device__ __forceinline__ void gather_node16(int node, int lane, float* a /*[8]*/) {
    int start = g_off[node];
    int d     = g_deg[node];
    const uint4* Z = reinterpret_cast<const uint4*>(g_z16);   // 32 uint4 per row
#pragma unroll
    for (int j = 0; j < 8; j++) a[j] = 0.f;
    int i = 0;
    for (; i + 4 <= d; i += 4) {
        int s0 = __ldg(&g_csr[start + i]);
        int s1 = __ldg(&g_csr[start + i + 1]);
        int s2 = __ldg(&g_csr[start + i + 2]);
        int s3 = __ldg(&g_csr[start + i + 3]);
        uint4 v0 = __ldg(Z + (size_t)s0 * 32 + lane);
        uint4 v1 = __ldg(Z + (size_t)s1 * 32 + lane);
        uint4 v2 = __ldg(Z + (size_t)s2 * 32 + lane);
        uint4 v3 = __ldg(Z + (size_t)s3 * 32 + lane);
        const uint32_t* ws[4] = { &v0.x, &v1.x, &v2.x, &v3.x };
#pragma unroll
        for (int e = 0; e < 4; e++) {
#pragma unroll
            for (int j = 0; j < 4; j++) {
                float2 f = __half22float2(*reinterpret_cast<const __half2*>(ws[e] + j));
                a[2 * j]     += f.x;
                a[2 * j + 1] += f.y;
            }
        }
    }
    for (; i < d; i++) {
        int s0 = __ldg(&g_csr[start + i]);
        uint4 v0 = __ldg(Z + (size_t)s0 * 32 + lane);
        const uint32_t* w = &v0.x;
#pragma unroll
        for (int j = 0; j < 4; j++) {
            float2 f = __half22float2(*reinterpret_cast<const __half2*>(w + j));
            a[2 * j]     += f.x;
            a[2 * j + 1] += f.y;
        }
    }
}

__global__ void agg1_kernel() {
    int node = (blockIdx.x * blockDim.x + threadIdx.x) >> 5;
    int lane = threadIdx.x & 31;
    if (node >= NN) return;
    float a[8];
    gather_node16(node, lane, a);
    uint4 o;
    uint32_t* w = &o.x;
#pragma unroll
    for (int j = 0; j < 4; j++) {
        __half2 hv = __floats2half2_rn(tanhf(a[2 * j]), tanhf(a[2 * j + 1]));
        w[j] = *reinterpret_cast<uint32_t*>(&hv);
    }
    __stcs(reinterpret_cast<uint4*>(g_h16) + (size_t)node * 32 + lane, o);
}

__global__ void agg2_pool_kernel(const int* __restrict__ seg) {
    int node = (blockIdx.x * blockDim.x + threadIdx.x) >> 5;
    int lane = threadIdx.x & 31;
    if (node >= NN) return;
    float a[8];
    gather_node16(node, lane, a);
    int s = __ldg(seg + node);
    float4* dp = reinterpret_cast<float4*>(g_sums + (size_t)s * HID + lane * 8);
    float4 t0 = make_float4(tanhf(a[0]), tanhf(a[1]), tanhf(a[2]), tanhf(a[3]));
    float4 t1 = make_float4(tanhf(a[4]), tanhf(a[5]), tanhf(a[6]), tanhf(a[7]));
    red_add_v4(dp,     t0);
    red_add_v4(dp + 1, t1);
    if (lane == 0) atomicAdd(&g_cnt[s], 1.0f);
}

__global__ void finalize_kernel(float* __restrict__ out) {
    int i = blockIdx.x * blockDim.x + threadIdx.x;
    if (i < NSLOTS * HID) {
        float c = g_cnt[i >> 8];
        out[i] = g_sums[i] / fmaxf(c, 1.0f);
    }
}

// ---------------- launch ----------------
extern "C" void kernel_launch(void* const* d_in, const int* in_sizes, int n_in,
                              void* d_out, int out_size) {
    const float* h    = (const float*)d_in[0];
    const float* W1   = (const float*)d_in[1];
    const float* b1   = (const float*)d_in[2];
    const float* W2   = (const float*)d_in[3];
    const float* b2   = (const float*)d_in[4];
    const int*   esrc = (const int*)d_in[5];
    const int*   edst = (const int*)d_in[6];
    const int*   seg  = (const int*)d_in[7];
    float*       out  = (float*)d_out;

    const int M = in_sizes[0] / HID;   // 100000

    static cudaStream_t s2 = nullptr;
    static cudaEvent_t  evA = nullptr, evB = nullptr;
    static int inited = 0;
    if (!inited) {
        cudaStreamCreateWithFlags(&s2, cudaStreamNonBlocking);
        cudaEventCreateWithFlags(&evA, cudaEventDisableTiming);
        cudaEventCreateWithFlags(&evB, cudaEventDisableTiming);
        cudaFuncSetAttribute(gemm_mma_kernel,
                             cudaFuncAttributeMaxDynamicSharedMemorySize,
                             GEMM_SMEM_BYTES);
        inited = 1;
    }

    dim3 gemm_grid(HID / 128, (M + 127) / 128);        // (2, 782)
    int  agg_blocks  = (M * 32 + 255) / 256;
    int  edge_blocks = (NE + 255) / 256;

    // ---- fork: CSR build on side stream ----
    cudaEventRecord(evA, 0);
    cudaStreamWaitEvent(s2, evA, 0);
    zero_misc_kernel<<<(NSLOTS * HID + 255) / 256, 256, 0, s2>>>();
    hist_kernel<<<edge_blocks, 256, 0, s2>>>(edst);
    scan1_kernel<<<NSCAN, 256, 0, s2>>>();
    scan2_kernel<<<1, 32, 0, s2>>>();
    scan3_kernel<<<NSCAN, 256, 0, s2>>>();
    fill_csr_kernel<<<edge_blocks, 256, 0, s2>>>(esrc, edst);
    cudaEventRecord(evB, s2);

    // ---- main stream: GEMM1 (independent of CSR) ----
    gemm_mma_kernel<<<gemm_grid, 256, GEMM_SMEM_BYTES>>>(h, W1, b1, M, 0);

    // ---- join: CSR needed from here on ----
    cudaStreamWaitEvent(0, evB, 0);
    agg1_kernel<<<agg_blocks, 256>>>();

    gemm_mma_kernel<<<gemm_grid, 256, GEMM_SMEM_BYTES>>>(h, W2, b2, M, 1);
    agg2_pool_kernel<<<agg_blocks, 256>>>(seg);

    finalize_kernel<<<(NSLOTS * HID + 255) / 256, 256>>>(out);
}

// round 10
// speedup vs baseline: 1.2766x; 1.1373x over previous
#include <cuda_runtime.h>
#include <cuda_fp16.h>
#include <cstdint>

#define NN      100000
#define NE      1600000
#define HID     256
#define KDIM    256
#define NSLOTS  800
#define SCAN_BLK 1024
#define NSCAN   ((NN + SCAN_BLK - 1) / SCAN_BLK)   // 98

// ---------------- scratch ----------------
__device__ __align__(128) __half g_z16[(size_t)NN * HID];   // GEMM out (fp16)
__device__ __align__(128) __half g_h16[(size_t)NN * HID];   // tanh(agg1) (fp16)
__device__ __align__(128) float  g_sums[NSLOTS * HID];
__device__ float g_cnt [NSLOTS];
__device__ int   g_deg [NN];
__device__ int   g_off [NN];
__device__ int   g_cursor[NN];
__device__ int   g_part[NSCAN];
__device__ int   g_csr [NE];

// ---------------- helpers ----------------
__device__ __forceinline__ void red_add_v4(float4* p, const float4 v) {
    asm volatile("red.global.add.v4.f32 [%0], {%1, %2, %3, %4};"
                 :: "l"(p), "f"(v.x), "f"(v.y), "f"(v.z), "f"(v.w)
                 : "memory");
}

// ---------------- zero / CSR build ----------------
__global__ void zero_misc_kernel() {
    int i = blockIdx.x * blockDim.x + threadIdx.x;
    if (i < NN)            g_deg[i]  = 0;
    if (i < NSLOTS * HID)  g_sums[i] = 0.f;
    if (i < NSLOTS)        g_cnt[i]  = 0.f;
}
__global__ void hist_kernel(const int* __restrict__ edst) {
    int e = blockIdx.x * blockDim.x + threadIdx.x;
    if (e < NE) atomicAdd(&g_deg[edst[e]], 1);
}
__global__ void scan1_kernel() {
    __shared__ int sh[256];
    int tid = threadIdx.x;
    int base = blockIdx.x * SCAN_BLK + tid * 4;
    int s = 0;
    if (base < NN) {
        int4 v = *reinterpret_cast<const int4*>(g_deg + base);
        s = v.x + v.y + v.z + v.w;
    }
    sh[tid] = s; __syncthreads();
    for (int o = 128; o > 0; o >>= 1) {
        if (tid < o) sh[tid] += sh[tid + o];
        __syncthreads();
    }
    if (tid == 0) g_part[blockIdx.x] = sh[0];
}
__global__ void scan2_kernel() {
    int lane = threadIdx.x;
    int base = lane * 4;
    int v[4], tot = 0;
#pragma unroll
    for (int j = 0; j < 4; j++) {
        v[j] = (base + j < NSCAN) ? g_part[base + j] : 0;
        tot += v[j];
    }
    int inc = tot;
#pragma unroll
    for (int o = 1; o < 32; o <<= 1) {
        int n = __shfl_up_sync(0xFFFFFFFFu, inc, o);
        if (lane >= o) inc += n;
    }
    int run = inc - tot;
#pragma unroll
    for (int j = 0; j < 4; j++) {
        if (base + j < NSCAN) g_part[base + j] = run;
        run += v[j];
    }
}
__global__ void scan3_kernel() {
    __shared__ int sh[256];
    int tid = threadIdx.x;
    int base = blockIdx.x * SCAN_BLK + tid * 4;
    int4 v = make_int4(0, 0, 0, 0);
    if (base < NN) v = *reinterpret_cast<const int4*>(g_deg + base);
    int t = v.x + v.y + v.z + v.w;
    sh[tid] = t; __syncthreads();
    for (int o = 1; o < 256; o <<= 1) {
        int add = (tid >= o) ? sh[tid - o] : 0;
        __syncthreads();
        sh[tid] += add;
        __syncthreads();
    }
    int excl = sh[tid] - t + g_part[blockIdx.x];
    if (base < NN) {
        int4 o;
        o.x = excl; o.y = o.x + v.x; o.z = o.y + v.y; o.w = o.z + v.z;
        *reinterpret_cast<int4*>(g_off + base)    = o;
        *reinterpret_cast<int4*>(g_cursor + base) = o;
    }
}
__global__ void fill_csr_kernel(const int* __restrict__ esrc, const int* __restrict__ edst) {
    int e = blockIdx.x * blockDim.x + threadIdx.x;
    if (e >= NE) return;
    int d   = edst[e];
    int pos = atomicAdd(&g_cursor[d], 1);
    g_csr[pos] = esrc[e];
}

// ---------------- fp16 mma.sync m16n8k16 GEMM: g_z16 = fp16(A @ W + bias) ----
// CTA 128x128, BK=32 (2 k16 steps/chunk), 2-stage smem, 8 warps (2x4),
// warp tile 64x32. A frags: LDS.32 (stride-40 conflict-free); B frags:
// ldmatrix.x4.trans (stride-136 conflict-free).
#define BK      32
#define NCH     (KDIM / BK)            // 8
#define AS_H    40                     // halves per A row
#define BS_H    136                    // halves per B k-row
#define A_STG_H (128 * AS_H)           // 5120 halves
#define B_STG_H (BK * BS_H)            // 4352 halves
#define GEMM_SMEM_BYTES ((2 * A_STG_H + 2 * B_STG_H) * 2)   // 37888

__device__ __forceinline__ void mma_f16(float* d, const uint32_t* a, const uint32_t* b) {
    asm volatile(
        "mma.sync.aligned.m16n8k16.row.col.f32.f16.f16.f32 "
        "{%0,%1,%2,%3}, {%4,%5,%6,%7}, {%8,%9}, {%0,%1,%2,%3};"
        : "+f"(d[0]), "+f"(d[1]), "+f"(d[2]), "+f"(d[3])
        : "r"(a[0]), "r"(a[1]), "r"(a[2]), "r"(a[3]), "r"(b[0]), "r"(b[1]));
}
__device__ __forceinline__ void ldsm_x4_trans(uint32_t* r, uint32_t addr) {
    asm volatile("ldmatrix.sync.aligned.m8n8.x4.trans.shared.b16 {%0,%1,%2,%3}, [%4];"
                 : "=r"(r[0]), "=r"(r[1]), "=r"(r[2]), "=r"(r[3]) : "r"(addr));
}
__device__ __forceinline__ uint32_t pack_h2(float a, float b) {
    __half2 h = __floats2half2_rn(a, b);
    return *reinterpret_cast<uint32_t*>(&h);
}

__device__ __forceinline__ void gemm_fill(const float* __restrict__ A32, int useGH,
                                          const float* __restrict__ W,
                                          int m_base, int n_base, int M, int k0,
                                          __half* Af, __half* Bf, int tid) {
    // A: 128 rows x 32 k (half), 8B stores
#pragma unroll
    for (int l = 0; l < 4; l++) {
        int idx = tid + l * 256;
        int r   = idx >> 3;
        int c4  = (idx & 7) << 2;
        int gm  = m_base + r;
        uint2 o = make_uint2(0u, 0u);
        if (gm < M) {
            if (useGH) {
                o = __ldg(reinterpret_cast<const uint2*>(
                    g_h16 + (size_t)gm * KDIM + k0 + c4));
            } else {
                float4 v = *reinterpret_cast<const float4*>(
                    A32 + (size_t)gm * KDIM + k0 + c4);
                o.x = pack_h2(v.x, v.y);
                o.y = pack_h2(v.z, v.w);
            }
        }
        *reinterpret_cast<uint2*>(Af + r * AS_H + c4) = o;
    }
    // B: 32 k x 128 n (half)
#pragma unroll
    for (int l = 0; l < 4; l++) {
        int idx = tid + l * 256;
        int k   = idx >> 5;
        int n4  = (idx & 31) << 2;
        float4 v = *reinterpret_cast<const float4*>(
            W + (size_t)(k0 + k) * HID + n_base + n4);
        uint2 o;
        o.x = pack_h2(v.x, v.y);
        o.y = pack_h2(v.z, v.w);
        *reinterpret_cast<uint2*>(Bf + k * BS_H + n4) = o;
    }
}

__global__ __launch_bounds__(256, 2)
void gemm_mma_kernel(const float* __restrict__ A_in, const float* __restrict__ W,
                     const float* __restrict__ bias, int M, int useGH) {
    extern __shared__ __half smem[];

    const int tid    = threadIdx.x;
    const int wid    = tid >> 5;
    const int lane   = tid & 31;
    const int warp_m = wid >> 2;         // 0..1
    const int warp_n = wid & 3;          // 0..3
    const int m_base = blockIdx.y * 128;
    const int n_base = blockIdx.x * 128;

    __half* Asm[2] = { smem,               smem + A_STG_H };
    __half* Bsm[2] = { smem + 2 * A_STG_H, smem + 2 * A_STG_H + B_STG_H };
    uint32_t smem_u = (uint32_t)__cvta_generic_to_shared(smem);
    uint32_t Bu[2]  = { smem_u + 2 * A_STG_H * 2,
                        smem_u + (2 * A_STG_H + B_STG_H) * 2 };

    float acc[4][4][4];
#pragma unroll
    for (int i = 0; i < 4; i++)
#pragma unroll
        for (int j = 0; j < 4; j++)
#pragma unroll
            for (int f = 0; f < 4; f++) acc[i][j][f] = 0.f;

    gemm_fill(A_in, useGH, W, m_base, n_base, M, 0, Asm[0], Bsm[0], tid);
    __syncthreads();

    const int g   = lane >> 2;
    const int cth = lane & 3;
    // ldmatrix address components (per-thread, loop-invariant)
    const int ld_row = lane & 15;        // k-row within k16
    const int ld_grp = (lane >> 4) << 3; // n offset 0 or 8

    for (int c = 0; c < NCH; c++) {
        int cur = c & 1;
        const __half* As = Asm[cur];

        if (c + 1 < NCH)
            gemm_fill(A_in, useGH, W, m_base, n_base, M, (c + 1) * BK,
                      Asm[1 - cur], Bsm[1 - cur], tid);

#pragma unroll
        for (int ks = 0; ks < 2; ks++) {
            uint32_t bfr[4][2];
#pragma unroll
            for (int hn = 0; hn < 2; hn++) {
                uint32_t hidx = (uint32_t)((ks * 16 + ld_row) * BS_H
                                           + warp_n * 32 + hn * 16 + ld_grp);
                uint32_t r[4];
                ldsm_x4_trans(r, Bu[cur] + hidx * 2);
                bfr[2 * hn][0]     = r[0];
                bfr[2 * hn][1]     = r[1];
                bfr[2 * hn + 1][0] = r[2];
                bfr[2 * hn + 1][1] = r[3];
            }
#pragma unroll
            for (int mt = 0; mt < 4; mt++) {
                int base = (warp_m * 64 + mt * 16 + g) * AS_H + ks * 16 + 2 * cth;
                uint32_t afr[4];
                afr[0] = *reinterpret_cast<const uint32_t*>(As + base);            // (g,   k)
                afr[1] = *reinterpret_cast<const uint32_t*>(As + base + 8 * AS_H); // (g+8, k)
                afr[2] = *reinterpret_cast<const uint32_t*>(As + base + 8);        // (g,   k+8)
                afr[3] = *reinterpret_cast<const uint32_t*>(As + base + 8 * AS_H + 8);
#pragma unroll
                for (int nt = 0; nt < 4; nt++)
                    mma_f16(acc[mt][nt], afr, bfr[nt]);
            }
        }
        __syncthreads();
    }

    // epilogue: fp32 acc + bias -> fp16 store
#pragma unroll
    for (int mt = 0; mt < 4; mt++) {
        int r0 = m_base + warp_m * 64 + mt * 16 + g;
        int r1 = r0 + 8;
#pragma unroll
        for (int nt = 0; nt < 4; nt++) {
            int col = n_base + warp_n * 32 + nt * 8 + cth * 2;
            float b0 = __ldg(bias + col);
            float b1 = __ldg(bias + col + 1);
            if (r0 < M) {
                uint32_t o = pack_h2(acc[mt][nt][0] + b0, acc[mt][nt][1] + b1);
                *reinterpret_cast<uint32_t*>(g_z16 + (size_t)r0 * HID + col) = o;
            }
            if (r1 < M) {
                uint32_t o = pack_h2(acc[mt][nt][2] + b0, acc[mt][nt][3] + b1);
                *reinterpret_cast<uint32_t*>(g_z16 + (size_t)r1 * HID + col) = o;
            }
        }
    }
}

// ---------------- fp16 gather-aggregate (CSR), warp per node, unroll 8 -------
__device__ __forceinline__ void acc_row(float* a, const uint4& v) {
    const uint32_t* w = &v.x;
#pragma unroll
    for (int j = 0; j < 4; j++) {
        float2 f = __half22float2(*reinterpret_cast<const __half2*>(w + j));
        a[2 * j]     += f.x;
        a[2 * j + 1] += f.y;
    }
}

__device__ __forceinline__ void gather_node16(int node, int lane, float* a /*[8]*/) {
    int start = g_off[node];
    int d     = g_deg[node];
    const uint4* Z = reinterpret_cast<const uint4*>(g_z16);   // 32 uint4 per row
#pragma unroll
    for (int j = 0; j < 8; j++) a[j] = 0.f;
    int i = 0;
    for (; i + 8 <= d; i += 8) {
        int s[8];
#pragma unroll
        for (int j = 0; j < 8; j++) s[j] = __ldg(&g_csr[start + i + j]);
        uint4 v[8];
#pragma unroll
        for (int j = 0; j < 8; j++) v[j] = __ldg(Z + (size_t)s[j] * 32 + lane);
#pragma unroll
        for (int j = 0; j < 8; j++) acc_row(a, v[j]);
    }
    for (; i < d; i++) {
        int s0 = __ldg(&g_csr[start + i]);
        uint4 v0 = __ldg(Z + (size_t)s0 * 32 + lane);
        acc_row(a, v0);
    }
}

__global__ void agg1_kernel() {
    int node = (blockIdx.x * blockDim.x + threadIdx.x) >> 5;
    int lane = threadIdx.x & 31;
    if (node >= NN) return;
    float a[8];
    gather_node16(node, lane, a);
    uint4 o;
    uint32_t* w = &o.x;
#pragma unroll
    for (int j = 0; j < 4; j++)
        w[j] = pack_h2(tanhf(a[2 * j]), tanhf(a[2 * j + 1]));
    __stcs(reinterpret_cast<uint4*>(g_h16) + (size_t)node * 32 + lane, o);
}

__global__ void agg2_pool_kernel(const int* __restrict__ seg) {
    int node = (blockIdx.x * blockDim.x + threadIdx.x) >> 5;
    int lane = threadIdx.x & 31;
    if (node >= NN) return;
    float a[8];
    gather_node16(node, lane, a);
    int s = __ldg(seg + node);
    float4* dp = reinterpret_cast<float4*>(g_sums + (size_t)s * HID + lane * 8);
    float4 t0 = make_float4(tanhf(a[0]), tanhf(a[1]), tanhf(a[2]), tanhf(a[3]));
    float4 t1 = make_float4(tanhf(a[4]), tanhf(a[5]), tanhf(a[6]), tanhf(a[7]));
    red_add_v4(dp,     t0);
    red_add_v4(dp + 1, t1);
    if (lane == 0) atomicAdd(&g_cnt[s], 1.0f);
}

__global__ void finalize_kernel(float* __restrict__ out) {
    int i = blockIdx.x * blockDim.x + threadIdx.x;
    if (i < NSLOTS * HID) {
        float c = g_cnt[i >> 8];
        out[i] = g_sums[i] / fmaxf(c, 1.0f);
    }
}

// ---------------- launch ----------------
extern "C" void kernel_launch(void* const* d_in, const int* in_sizes, int n_in,
                              void* d_out, int out_size) {
    const float* h    = (const float*)d_in[0];
    const float* W1   = (const float*)d_in[1];
    const float* b1   = (const float*)d_in[2];
    const float* W2   = (const float*)d_in[3];
    const float* b2   = (const float*)d_in[4];
    const int*   esrc = (const int*)d_in[5];
    const int*   edst = (const int*)d_in[6];
    const int*   seg  = (const int*)d_in[7];
    float*       out  = (float*)d_out;

    const int M = in_sizes[0] / HID;   // 100000

    static cudaStream_t s2 = nullptr;
    static cudaEvent_t  evA = nullptr, evB = nullptr;
    static int inited = 0;
    if (!inited) {
        cudaStreamCreateWithFlags(&s2, cudaStreamNonBlocking);
        cudaEventCreateWithFlags(&evA, cudaEventDisableTiming);
        cudaEventCreateWithFlags(&evB, cudaEventDisableTiming);
        cudaFuncSetAttribute(gemm_mma_kernel,
                             cudaFuncAttributeMaxDynamicSharedMemorySize,
                             GEMM_SMEM_BYTES);
        inited = 1;
    }

    dim3 gemm_grid(HID / 128, (M + 127) / 128);        // (2, 782)
    int  agg_blocks  = (M * 32 + 255) / 256;
    int  edge_blocks = (NE + 255) / 256;

    // ---- fork: CSR build on side stream ----
    cudaEventRecord(evA, 0);
    cudaStreamWaitEvent(s2, evA, 0);
    zero_misc_kernel<<<(NSLOTS * HID + 255) / 256, 256, 0, s2>>>();
    hist_kernel<<<edge_blocks, 256, 0, s2>>>(edst);
    scan1_kernel<<<NSCAN, 256, 0, s2>>>();
    scan2_kernel<<<1, 32, 0, s2>>>();
    scan3_kernel<<<NSCAN, 256, 0, s2>>>();
    fill_csr_kernel<<<edge_blocks, 256, 0, s2>>>(esrc, edst);
    cudaEventRecord(evB, s2);

    // ---- main stream: GEMM1 (independent of CSR) ----
    gemm_mma_kernel<<<gemm_grid, 256, GEMM_SMEM_BYTES>>>(h, W1, b1, M, 0);

    // ---- join: CSR needed from here on ----
    cudaStreamWaitEvent(0, evB, 0);
    agg1_kernel<<<agg_blocks, 256>>>();

    gemm_mma_kernel<<<gemm_grid, 256, GEMM_SMEM_BYTES>>>(h, W2, b2, M, 1);
    agg2_pool_kernel<<<agg_blocks, 256>>>(seg);

    finalize_kernel<<<(NSLOTS * HID + 255) / 256, 256>>>(out);
}

// round 11
// speedup vs baseline: 1.8224x; 1.4275x over previous
#include <cuda_runtime.h>
#include <cuda_fp16.h>
#include <cstdint>

#define NN      100000
#define NE      1600000
#define HID     256
#define KDIM    256
#define NSLOTS  800
#define SCAN_BLK 1024
#define NSCAN   ((NN + SCAN_BLK - 1) / SCAN_BLK)   // 98

// ---------------- scratch ----------------
__device__ __align__(128) __half g_z16[(size_t)NN * HID];   // GEMM out (fp16)
__device__ __align__(128) __half g_h16[(size_t)NN * HID];   // tanh(agg1) (fp16)
__device__ __align__(128) __half g_x16[(size_t)NN * HID];   // fp16 input x
__device__ __align__(128) __half g_w16[2 * KDIM * HID];     // fp16 W1, W2
__device__ __align__(128) float  g_sums[NSLOTS * HID];
__device__ float g_cnt [NSLOTS];
__device__ int   g_deg [NN];
__device__ int   g_off [NN];
__device__ int   g_cursor[NN];
__device__ int   g_part[NSCAN];
__device__ int   g_csr [NE];

// ---------------- helpers ----------------
__device__ __forceinline__ void red_add_v4(float4* p, const float4 v) {
    asm volatile("red.global.add.v4.f32 [%0], {%1, %2, %3, %4};"
                 :: "l"(p), "f"(v.x), "f"(v.y), "f"(v.z), "f"(v.w)
                 : "memory");
}
__device__ __forceinline__ uint32_t pack_h2(float a, float b) {
    __half2 h = __floats2half2_rn(a, b);
    return *reinterpret_cast<uint32_t*>(&h);
}

// ---------------- zero / CSR build ----------------
__global__ void zero_misc_kernel() {
    int i = blockIdx.x * blockDim.x + threadIdx.x;
    if (i < NN)            g_deg[i]  = 0;
    if (i < NSLOTS * HID)  g_sums[i] = 0.f;
    if (i < NSLOTS)        g_cnt[i]  = 0.f;
}
__global__ void hist_kernel(const int* __restrict__ edst) {
    int e = blockIdx.x * blockDim.x + threadIdx.x;
    if (e < NE) atomicAdd(&g_deg[edst[e]], 1);
}
__global__ void scan1_kernel() {
    __shared__ int sh[256];
    int tid = threadIdx.x;
    int base = blockIdx.x * SCAN_BLK + tid * 4;
    int s = 0;
    if (base < NN) {
        int4 v = *reinterpret_cast<const int4*>(g_deg + base);
        s = v.x + v.y + v.z + v.w;
    }
    sh[tid] = s; __syncthreads();
    for (int o = 128; o > 0; o >>= 1) {
        if (tid < o) sh[tid] += sh[tid + o];
        __syncthreads();
    }
    if (tid == 0) g_part[blockIdx.x] = sh[0];
}
__global__ void scan2_kernel() {
    int lane = threadIdx.x;
    int base = lane * 4;
    int v[4], tot = 0;
#pragma unroll
    for (int j = 0; j < 4; j++) {
        v[j] = (base + j < NSCAN) ? g_part[base + j] : 0;
        tot += v[j];
    }
    int inc = tot;
#pragma unroll
    for (int o = 1; o < 32; o <<= 1) {
        int n = __shfl_up_sync(0xFFFFFFFFu, inc, o);
        if (lane >= o) inc += n;
    }
    int run = inc - tot;
#pragma unroll
    for (int j = 0; j < 4; j++) {
        if (base + j < NSCAN) g_part[base + j] = run;
        run += v[j];
    }
}
__global__ void scan3_kernel() {
    __shared__ int sh[256];
    int tid = threadIdx.x;
    int base = blockIdx.x * SCAN_BLK + tid * 4;
    int4 v = make_int4(0, 0, 0, 0);
    if (base < NN) v = *reinterpret_cast<const int4*>(g_deg + base);
    int t = v.x + v.y + v.z + v.w;
    sh[tid] = t; __syncthreads();
    for (int o = 1; o < 256; o <<= 1) {
        int add = (tid >= o) ? sh[tid - o] : 0;
        __syncthreads();
        sh[tid] += add;
        __syncthreads();
    }
    int excl = sh[tid] - t + g_part[blockIdx.x];
    if (base < NN) {
        int4 o;
        o.x = excl; o.y = o.x + v.x; o.z = o.y + v.y; o.w = o.z + v.z;
        *reinterpret_cast<int4*>(g_off + base)    = o;
        *reinterpret_cast<int4*>(g_cursor + base) = o;
    }
}
__global__ void fill_csr_kernel(const int* __restrict__ esrc, const int* __restrict__ edst) {
    int e = blockIdx.x * blockDim.x + threadIdx.x;
    if (e >= NE) return;
    int d   = edst[e];
    int pos = atomicAdd(&g_cursor[d], 1);
    g_csr[pos] = esrc[e];
}

// ---------------- fp16 pre-conversion ----------------
__global__ void conv_x_kernel(const float* __restrict__ x) {
    size_t i = (size_t)blockIdx.x * 256 + threadIdx.x;   // 6.4M float4s
    float4 v = reinterpret_cast<const float4*>(x)[i];
    uint2 o;
    o.x = pack_h2(v.x, v.y);
    o.y = pack_h2(v.z, v.w);
    reinterpret_cast<uint2*>(g_x16)[i] = o;
}
__global__ void conv_w_kernel(const float* __restrict__ W1, const float* __restrict__ W2) {
    int i = blockIdx.x * 256 + threadIdx.x;              // 0..32767 float4s
    const float4* src = (i < 16384) ? reinterpret_cast<const float4*>(W1)
                                    : reinterpret_cast<const float4*>(W2) - 16384;
    float4 v = src[i];
    uint2 o;
    o.x = pack_h2(v.x, v.y);
    o.y = pack_h2(v.z, v.w);
    reinterpret_cast<uint2*>(g_w16)[i] = o;
}

// ---------------- fp16 mma.sync GEMM, cp.async 3-stage ----------------
// CTA 128x128, BK=32, warp tile 64x32 (8 warps, 2x4).
#define BK      32
#define NCH     (KDIM / BK)            // 8
#define AS_H    40                     // halves per A row (80B, 16B-aligned)
#define BS_H    136                    // halves per B k-row (272B, 16B-aligned)
#define A_STG_H (128 * AS_H)           // 5120 halves = 10240B
#define B_STG_H (BK * BS_H)            // 4352 halves = 8704B
#define NSTAGE  3
#define GEMM_SMEM_BYTES (NSTAGE * (A_STG_H + B_STG_H) * 2)   // 56832

__device__ __forceinline__ void mma_f16(float* d, const uint32_t* a, const uint32_t* b) {
    asm volatile(
        "mma.sync.aligned.m16n8k16.row.col.f32.f16.f16.f32 "
        "{%0,%1,%2,%3}, {%4,%5,%6,%7}, {%8,%9}, {%0,%1,%2,%3};"
        : "+f"(d[0]), "+f"(d[1]), "+f"(d[2]), "+f"(d[3])
        : "r"(a[0]), "r"(a[1]), "r"(a[2]), "r"(a[3]), "r"(b[0]), "r"(b[1]));
}
__device__ __forceinline__ void ldsm_x4_trans(uint32_t* r, uint32_t addr) {
    asm volatile("ldmatrix.sync.aligned.m8n8.x4.trans.shared.b16 {%0,%1,%2,%3}, [%4];"
                 : "=r"(r[0]), "=r"(r[1]), "=r"(r[2]), "=r"(r[3]) : "r"(addr));
}
__device__ __forceinline__ void cp16(uint32_t dst, const void* src, int sz) {
    asm volatile("cp.async.cg.shared.global [%0], [%1], 16, %2;"
                 :: "r"(dst), "l"(src), "r"(sz));
}

__device__ __forceinline__ void gemm_fill_async(const __half* __restrict__ A,
                                                const __half* __restrict__ Wp,
                                                int m_base, int n_base, int M, int k0,
                                                uint32_t Au, uint32_t Bu, int tid) {
    // A tile: 128 rows x 32 halves; 16B chunk = 8 halves; 4 chunks/row; 2/thread
#pragma unroll
    for (int l = 0; l < 2; l++) {
        int ch  = tid + l * 256;            // 0..511
        int r   = ch >> 2;
        int c8  = (ch & 3) << 3;            // half offset
        int gm  = m_base + r;
        cp16(Au + (r * AS_H + c8) * 2,
             A + (size_t)((gm < M) ? gm : 0) * KDIM + k0 + c8,
             (gm < M) ? 16 : 0);
    }
    // B tile: 32 k-rows x 128 halves; 16 chunks/row; 2/thread
#pragma unroll
    for (int l = 0; l < 2; l++) {
        int ch  = tid + l * 256;            // 0..511
        int k   = ch >> 4;
        int n8  = (ch & 15) << 3;
        cp16(Bu + (k * BS_H + n8) * 2,
             Wp + (size_t)(k0 + k) * HID + n_base + n8, 16);
    }
    asm volatile("cp.async.commit_group;" ::: "memory");
}

__global__ __launch_bounds__(256, 2)
void gemm_mma_kernel(const float* __restrict__ bias, int M, int a_sel, int w_sel) {
    extern __shared__ __half smem[];
    const __half* __restrict__ A  = a_sel ? g_h16 : g_x16;
    const __half* __restrict__ Wp = g_w16 + (size_t)w_sel * KDIM * HID;

    const int tid    = threadIdx.x;
    const int wid    = tid >> 5;
    const int lane   = tid & 31;
    const int warp_m = wid >> 2;
    const int warp_n = wid & 3;
    const int m_base = blockIdx.y * 128;
    const int n_base = blockIdx.x * 128;

    uint32_t smem_u = (uint32_t)__cvta_generic_to_shared(smem);
    const __half* As[NSTAGE];
    uint32_t Au[NSTAGE], Bu[NSTAGE];
#pragma unroll
    for (int s = 0; s < NSTAGE; s++) {
        As[s] = smem + s * A_STG_H;
        Au[s] = smem_u + s * A_STG_H * 2;
        Bu[s] = smem_u + (NSTAGE * A_STG_H + s * B_STG_H) * 2;
    }

    float acc[4][4][4];
#pragma unroll
    for (int i = 0; i < 4; i++)
#pragma unroll
        for (int j = 0; j < 4; j++)
#pragma unroll
            for (int f = 0; f < 4; f++) acc[i][j][f] = 0.f;

    gemm_fill_async(A, Wp, m_base, n_base, M, 0,  Au[0], Bu[0], tid);
    gemm_fill_async(A, Wp, m_base, n_base, M, BK, Au[1], Bu[1], tid);

    const int g      = lane >> 2;
    const int cth    = lane & 3;
    const int ld_row = lane & 15;
    const int ld_grp = (lane >> 4) << 3;

    for (int c = 0; c < NCH; c++) {
        int s = c % NSTAGE;
        if (c == NCH - 1)
            asm volatile("cp.async.wait_group 0;" ::: "memory");
        else
            asm volatile("cp.async.wait_group 1;" ::: "memory");
        __syncthreads();

        if (c + 2 < NCH)
            gemm_fill_async(A, Wp, m_base, n_base, M, (c + 2) * BK,
                            Au[(c + 2) % NSTAGE], Bu[(c + 2) % NSTAGE], tid);

        const __half* Ac = As[s];
#pragma unroll
        for (int ks = 0; ks < 2; ks++) {
            uint32_t bfr[4][2];
#pragma unroll
            for (int hn = 0; hn < 2; hn++) {
                uint32_t hidx = (uint32_t)((ks * 16 + ld_row) * BS_H
                                           + warp_n * 32 + hn * 16 + ld_grp);
                uint32_t r[4];
                ldsm_x4_trans(r, Bu[s] + hidx * 2);
                bfr[2 * hn][0]     = r[0];
                bfr[2 * hn][1]     = r[1];
                bfr[2 * hn + 1][0] = r[2];
                bfr[2 * hn + 1][1] = r[3];
            }
#pragma unroll
            for (int mt = 0; mt < 4; mt++) {
                int base = (warp_m * 64 + mt * 16 + g) * AS_H + ks * 16 + 2 * cth;
                uint32_t afr[4];
                afr[0] = *reinterpret_cast<const uint32_t*>(Ac + base);
                afr[1] = *reinterpret_cast<const uint32_t*>(Ac + base + 8 * AS_H);
                afr[2] = *reinterpret_cast<const uint32_t*>(Ac + base + 8);
                afr[3] = *reinterpret_cast<const uint32_t*>(Ac + base + 8 * AS_H + 8);
#pragma unroll
                for (int nt = 0; nt < 4; nt++)
                    mma_f16(acc[mt][nt], afr, bfr[nt]);
            }
        }
        __syncthreads();
    }

    // epilogue: fp32 acc + bias -> fp16 store
#pragma unroll
    for (int mt = 0; mt < 4; mt++) {
        int r0 = m_base + warp_m * 64 + mt * 16 + g;
        int r1 = r0 + 8;
#pragma unroll
        for (int nt = 0; nt < 4; nt++) {
            int col = n_base + warp_n * 32 + nt * 8 + cth * 2;
            float b0 = __ldg(bias + col);
            float b1 = __ldg(bias + col + 1);
            if (r0 < M) {
                uint32_t o = pack_h2(acc[mt][nt][0] + b0, acc[mt][nt][1] + b1);
                *reinterpret_cast<uint32_t*>(g_z16 + (size_t)r0 * HID + col) = o;
            }
            if (r1 < M) {
                uint32_t o = pack_h2(acc[mt][nt][2] + b0, acc[mt][nt][3] + b1);
                *reinterpret_cast<uint32_t*>(g_z16 + (size_t)r1 * HID + col) = o;
            }
        }
    }
}

// ---------------- fp16 gather-aggregate (CSR), warp per node, unroll 8 -------
__device__ __forceinline__ void acc_row(float* a, const uint4& v) {
    const uint32_t* w = &v.x;
#pragma unroll
    for (int j = 0; j < 4; j++) {
        float2 f = __half22float2(*reinterpret_cast<const __half2*>(w + j));
        a[2 * j]     += f.x;
        a[2 * j + 1] += f.y;
    }
}

__device__ __forceinline__ void gather_node16(int node, int lane, float* a /*[8]*/) {
    int start = g_off[node];
    int d     = g_deg[node];
    const uint4* Z = reinterpret_cast<const uint4*>(g_z16);   // 32 uint4 per row
#pragma unroll
    for (int j = 0; j < 8; j++) a[j] = 0.f;
    int i = 0;
    for (; i + 8 <= d; i += 8) {
        int s[8];
#pragma unroll
        for (int j = 0; j < 8; j++) s[j] = __ldg(&g_csr[start + i + j]);
        uint4 v[8];
#pragma unroll
        for (int j = 0; j < 8; j++) v[j] = __ldg(Z + (size_t)s[j] * 32 + lane);
#pragma unroll
        for (int j = 0; j < 8; j++) acc_row(a, v[j]);
    }
    for (; i < d; i++) {
        int s0 = __ldg(&g_csr[start + i]);
        uint4 v0 = __ldg(Z + (size_t)s0 * 32 + lane);
        acc_row(a, v0);
    }
}

__global__ void agg1_kernel() {
    int node = (blockIdx.x * blockDim.x + threadIdx.x) >> 5;
    int lane = threadIdx.x & 31;
    if (node >= NN) return;
    float a[8];
    gather_node16(node, lane, a);
    uint4 o;
    uint32_t* w = &o.x;
#pragma unroll
    for (int j = 0; j < 4; j++)
        w[j] = pack_h2(tanhf(a[2 * j]), tanhf(a[2 * j + 1]));
    __stcs(reinterpret_cast<uint4*>(g_h16) + (size_t)node * 32 + lane, o);
}

__global__ void agg2_pool_kernel(const int* __restrict__ seg) {
    int node = (blockIdx.x * blockDim.x + threadIdx.x) >> 5;
    int lane = threadIdx.x & 31;
    if (node >= NN) return;
    float a[8];
    gather_node16(node, lane, a);
    int s = __ldg(seg + node);
    float4* dp = reinterpret_cast<float4*>(g_sums + (size_t)s * HID + lane * 8);
    float4 t0 = make_float4(tanhf(a[0]), tanhf(a[1]), tanhf(a[2]), tanhf(a[3]));
    float4 t1 = make_float4(tanhf(a[4]), tanhf(a[5]), tanhf(a[6]), tanhf(a[7]));
    red_add_v4(dp,     t0);
    red_add_v4(dp + 1, t1);
    if (lane == 0) atomicAdd(&g_cnt[s], 1.0f);
}

__global__ void finalize_kernel(float* __restrict__ out) {
    int i = blockIdx.x * blockDim.x + threadIdx.x;
    if (i < NSLOTS * HID) {
        float c = g_cnt[i >> 8];
        out[i] = g_sums[i] / fmaxf(c, 1.0f);
    }
}

// ---------------- launch ----------------
extern "C" void kernel_launch(void* const* d_in, const int* in_sizes, int n_in,
                              void* d_out, int out_size) {
    const float* h    = (const float*)d_in[0];
    const float* W1   = (const float*)d_in[1];
    const float* b1   = (const float*)d_in[2];
    const float* W2   = (const float*)d_in[3];
    const float* b2   = (const float*)d_in[4];
    const int*   esrc = (const int*)d_in[5];
    const int*   edst = (const int*)d_in[6];
    const int*   seg  = (const int*)d_in[7];
    float*       out  = (float*)d_out;

    const int M = in_sizes[0] / HID;   // 100000

    static cudaStream_t s2 = nullptr;
    static cudaEvent_t  evA = nullptr, evB = nullptr;
    static int inited = 0;
    if (!inited) {
        cudaStreamCreateWithFlags(&s2, cudaStreamNonBlocking);
        cudaEventCreateWithFlags(&evA, cudaEventDisableTiming);
        cudaEventCreateWithFlags(&evB, cudaEventDisableTiming);
        cudaFuncSetAttribute(gemm_mma_kernel,
                             cudaFuncAttributeMaxDynamicSharedMemorySize,
                             GEMM_SMEM_BYTES);
        inited = 1;
    }

    dim3 gemm_grid(HID / 128, (M + 127) / 128);        // (2, 782)
    int  agg_blocks  = (M * 32 + 255) / 256;
    int  edge_blocks = (NE + 255) / 256;

    // ---- fork: CSR build on side stream ----
    cudaEventRecord(evA, 0);
    cudaStreamWaitEvent(s2, evA, 0);
    zero_misc_kernel<<<(NSLOTS * HID + 255) / 256, 256, 0, s2>>>();
    hist_kernel<<<edge_blocks, 256, 0, s2>>>(edst);
    scan1_kernel<<<NSCAN, 256, 0, s2>>>();
    scan2_kernel<<<1, 32, 0, s2>>>();
    scan3_kernel<<<NSCAN, 256, 0, s2>>>();
    fill_csr_kernel<<<edge_blocks, 256, 0, s2>>>(esrc, edst);
    cudaEventRecord(evB, s2);

    // ---- main stream: convert + GEMM1 (overlaps CSR build) ----
    conv_x_kernel<<<(NN * HID / 4) / 256, 256>>>(h);
    conv_w_kernel<<<128, 256>>>(W1, W2);
    gemm_mma_kernel<<<gemm_grid, 256, GEMM_SMEM_BYTES>>>(b1, M, 0, 0);

    // ---- join: CSR needed from here on ----
    cudaStreamWaitEvent(0, evB, 0);
    agg1_kernel<<<agg_blocks, 256>>>();

    gemm_mma_kernel<<<gemm_grid, 256, GEMM_SMEM_BYTES>>>(b2, M, 1, 1);
    agg2_pool_kernel<<<agg_blocks, 256>>>(seg);

    finalize_kernel<<<(NSLOTS * HID + 255) / 256, 256>>>(out);
}